// round 6
// baseline (speedup 1.0000x reference)
#include <cuda_runtime.h>
#include <float.h>

#define BN 512
#define DN 256
#define NT 16            // 512 / 32 tiles per dim
#define NBLK 136         // NT*(NT+1)/2 upper-triangular tiles

// Scratch (no allocations allowed)
__device__ float g_pd[BN * BN];
__device__ float g_ploss[BN];
__device__ int   g_pcnt[BN];
__device__ unsigned int g_arrive;  // device-wide barrier counter (reset each call)
__device__ unsigned int g_done;    // done counter (reset each call)

union SmemU {
    struct {
        float As[4][32][32];   // also reused as partial-sum scratch
        float Bs[4][32][32];
        float sq[2][32];
    } pd;
    struct {
        int   lab[BN];
        float row[4][BN];
    } mine;
};

// ---------------------------------------------------------------------------
// Single fused kernel, 136 CTAs x 256 threads:
//   Phase 1: symmetric pairwise sq-distance GEMM, split-K x4 (4 groups x 64)
//   Phase 2: device-wide barrier (all CTAs co-resident)
//   Phase 3: warp-per-anchor semi-hard mining (warps 0-3 of CTAs 0..127)
//   Phase 4: last-done CTA -> deterministic final reduction, counter reset
// ---------------------------------------------------------------------------
__global__ void __launch_bounds__(256) triplet_fused(const float* __restrict__ emb,
                                                     const int* __restrict__ labels,
                                                     float* __restrict__ out) {
    __shared__ SmemU sm;
    const int tid = threadIdx.x;
    const int lane = tid & 31, widx = tid >> 5;
    const unsigned FULL = 0xffffffffu;

    // ---- decode linear block -> (ti, tj), ti <= tj ----
    int b = blockIdx.x, ti = 0;
    while (b >= NT - ti) { b -= NT - ti; ti++; }
    const int tj = ti + b;
    const int i0 = ti * 32, j0 = tj * 32;

    // =========================== Phase 1: pd GEMM ===========================
    // norms: 4 threads per row, 64 rows (32 A + 32 B), 64 floats each
    {
        const int rowid = tid >> 2;            // 0..63
        const int quart = tid & 3;             // 0..3
        const int which = rowid >> 5;          // 0: A rows, 1: B rows
        const int r     = rowid & 31;
        const int row   = (which ? j0 : i0) + r;
        const float4* p = (const float4*)(emb + row * DN + quart * 64);
        float s0 = 0.f, s1 = 0.f;
        #pragma unroll
        for (int i = 0; i < 16; i += 2) {
            float4 v;
            v = p[i + 0]; s0 = fmaf(v.x, v.x, fmaf(v.y, v.y, fmaf(v.z, v.z, fmaf(v.w, v.w, s0))));
            v = p[i + 1]; s1 = fmaf(v.x, v.x, fmaf(v.y, v.y, fmaf(v.z, v.z, fmaf(v.w, v.w, s1))));
        }
        float s = s0 + s1;
        s += __shfl_xor_sync(FULL, s, 1);
        s += __shfl_xor_sync(FULL, s, 2);
        if (quart == 0) sm.pd.sq[which][r] = s;
    }

    // split-K x4 GEMM, 4x4 microtile. Group g covers k in [g*64, g*64+64),
    // processed as two 32-wide chunks.
    const int t  = tid & 63;
    const int g  = tid >> 6;               // 0..3
    const int lr = t >> 1;                 // load row 0..31
    const int half = t & 1;                // k-half within 32-chunk
    const int ty = t >> 3;                 // 0..7 -> 4 i-rows
    const int tx = t & 7;                  // 0..7 -> 4 j-cols

    float acc[4][4] = {};
    {
        const float* Arow = emb + (i0 + lr) * DN + g * 64;
        const float* Brow = emb + (j0 + lr) * DN + g * 64;

        #pragma unroll
        for (int c0 = 0; c0 < 64; c0 += 32) {
            __syncthreads();
            #pragma unroll
            for (int e = 0; e < 4; e++) {
                const int ko = half * 16 + e * 4;
                float4 a4 = *(const float4*)(Arow + c0 + ko);
                float4 b4 = *(const float4*)(Brow + c0 + ko);
                sm.pd.As[g][ko + 0][lr] = a4.x; sm.pd.As[g][ko + 1][lr] = a4.y;
                sm.pd.As[g][ko + 2][lr] = a4.z; sm.pd.As[g][ko + 3][lr] = a4.w;
                sm.pd.Bs[g][ko + 0][lr] = b4.x; sm.pd.Bs[g][ko + 1][lr] = b4.y;
                sm.pd.Bs[g][ko + 2][lr] = b4.z; sm.pd.Bs[g][ko + 3][lr] = b4.w;
            }
            __syncthreads();
            #pragma unroll
            for (int kk = 0; kk < 32; kk++) {
                float4 av = *(const float4*)&sm.pd.As[g][kk][ty << 2];
                float4 bv = *(const float4*)&sm.pd.Bs[g][kk][tx << 2];
                float ar[4] = {av.x, av.y, av.z, av.w};
                float br[4] = {bv.x, bv.y, bv.z, bv.w};
                #pragma unroll
                for (int u = 0; u < 4; u++)
                    #pragma unroll
                    for (int v = 0; v < 4; v++)
                        acc[u][v] = fmaf(ar[u], br[v], acc[u][v]);
            }
        }
    }

    // combine 4 k-group partials (groups 1..3 -> smem scratch, group 0 sums)
    __syncthreads();
    if (g > 0) {
        float* dst = &sm.pd.As[0][0][0] + ((g - 1) * 64 + t) * 16;
        #pragma unroll
        for (int u = 0; u < 4; u++)
            #pragma unroll
            for (int v = 0; v < 4; v++) dst[u * 4 + v] = acc[u][v];
    }
    __syncthreads();
    if (g == 0) {
        const float* p1 = &sm.pd.As[0][0][0] + (0 * 64 + t) * 16;
        const float* p2 = &sm.pd.As[0][0][0] + (1 * 64 + t) * 16;
        const float* p3 = &sm.pd.As[0][0][0] + (2 * 64 + t) * 16;
        float d[4][4];
        #pragma unroll
        for (int u = 0; u < 4; u++) {
            const int gi = i0 + (ty << 2) + u;
            const float sqi = sm.pd.sq[0][(ty << 2) + u];
            #pragma unroll
            for (int v = 0; v < 4; v++) {
                const int gj = j0 + (tx << 2) + v;
                const int e = u * 4 + v;
                const float dot = ((acc[u][v] + p1[e]) + (p2[e] + p3[e]));
                float val = fmaxf(sqi + sm.pd.sq[1][(tx << 2) + v] - 2.f * dot, 0.f);
                if (gi == gj) val = 0.f;
                d[u][v] = val;
            }
            *(float4*)(g_pd + gi * BN + j0 + (tx << 2)) =
                make_float4(d[u][0], d[u][1], d[u][2], d[u][3]);
        }
        if (ti != tj) {
            #pragma unroll
            for (int v = 0; v < 4; v++) {
                const int gj = j0 + (tx << 2) + v;
                *(float4*)(g_pd + gj * BN + i0 + (ty << 2)) =
                    make_float4(d[0][v], d[1][v], d[2][v], d[3][v]);
            }
        }
    }

    // ======================= Phase 2: device barrier ========================
    __syncthreads();
    if (tid == 0) {
        __threadfence();                       // publish g_pd writes
        atomicAdd(&g_arrive, 1u);
        while (*(volatile unsigned int*)&g_arrive < NBLK) { __nanosleep(32); }
    }
    __syncthreads();
    __threadfence();                           // acquire: g_pd visible

    // ========================= Phase 3: mining ==============================
    const int cb = blockIdx.x;
    if (cb < BN / 4) {
        for (int k = tid; k < BN; k += 256) sm.mine.lab[k] = labels[k];
        __syncthreads();

        if (widx < 4) {
            const int j = cb * 4 + widx;       // anchor
            const int lj = sm.mine.lab[j];
            const float* rowp = g_pd + j * BN;

            float v[16];
            unsigned nmask = 0, pmask = 0;
            #pragma unroll
            for (int c = 0; c < 16; c++) {
                const int k = c * 32 + lane;
                v[c] = rowp[k];
                sm.mine.row[widx][k] = v[c];
                const bool same = (sm.mine.lab[k] == lj);
                if (!same) nmask |= (1u << c);
                if (same && k != j) pmask |= (1u << c);
            }

            float mx = -FLT_MAX, mn = FLT_MAX;
            #pragma unroll
            for (int c = 0; c < 16; c++) {
                if ((nmask >> c) & 1) mx = fmaxf(mx, v[c]);
                mn = fminf(mn, v[c]);
            }
            #pragma unroll
            for (int o = 16; o; o >>= 1) {
                mx = fmaxf(mx, __shfl_xor_sync(FULL, mx, o));
                mn = fminf(mn, __shfl_xor_sync(FULL, mn, o));
            }
            const float ninside = (mx > -FLT_MAX) ? mx : mn;

            float wsum = 0.f;
            int cnt = 0;
            int pend = -1;
            #pragma unroll 1
            for (int c = 0; c < 16; c++) {
                unsigned pm = __ballot_sync(FULL, (pmask >> c) & 1);
                while (pm) {
                    const int bb = __ffs(pm) - 1;
                    pm &= pm - 1;
                    const int i = c * 32 + bb;
                    cnt++;
                    if (pend < 0) { pend = i; continue; }
                    const float t1 = sm.mine.row[widx][pend];
                    const float t2 = sm.mine.row[widx][i];
                    float m1 = FLT_MAX, m2 = FLT_MAX;
                    #pragma unroll
                    for (int cc = 0; cc < 16; cc++) {
                        if ((nmask >> cc) & 1) {
                            const float x = v[cc];
                            if (x > t1) m1 = fminf(m1, x);
                            if (x > t2) m2 = fminf(m2, x);
                        }
                    }
                    #pragma unroll
                    for (int o = 16; o; o >>= 1) {
                        m1 = fminf(m1, __shfl_xor_sync(FULL, m1, o));
                        m2 = fminf(m2, __shfl_xor_sync(FULL, m2, o));
                    }
                    const float semi1 = (m1 < FLT_MAX) ? m1 : ninside;
                    const float semi2 = (m2 < FLT_MAX) ? m2 : ninside;
                    wsum += fmaxf(1.0f + t1 - semi1, 0.f);
                    wsum += fmaxf(1.0f + t2 - semi2, 0.f);
                    pend = -1;
                }
            }
            if (pend >= 0) {
                const float t1 = sm.mine.row[widx][pend];
                float m1 = FLT_MAX;
                #pragma unroll
                for (int cc = 0; cc < 16; cc++) {
                    if ((nmask >> cc) & 1) {
                        const float x = v[cc];
                        if (x > t1) m1 = fminf(m1, x);
                    }
                }
                #pragma unroll
                for (int o = 16; o; o >>= 1)
                    m1 = fminf(m1, __shfl_xor_sync(FULL, m1, o));
                const float semi1 = (m1 < FLT_MAX) ? m1 : ninside;
                wsum += fmaxf(1.0f + t1 - semi1, 0.f);
            }

            if (lane == 0) {
                g_ploss[j] = wsum;
                g_pcnt[j]  = cnt;
            }
        }
        __syncthreads();
    }

    // ================= Phase 4: last CTA -> final reduction =================
    __shared__ int s_last;
    if (tid == 0) {
        __threadfence();
        const unsigned int vd = atomicAdd(&g_done, 1u);
        s_last = (vd == (unsigned)(NBLK - 1)) ? 1 : 0;
    }
    __syncthreads();

    if (s_last) {
        __threadfence();  // acquire
        float s = g_ploss[tid] + g_ploss[tid + 256];
        float c = (float)(g_pcnt[tid] + g_pcnt[tid + 256]);
        #pragma unroll
        for (int o = 16; o; o >>= 1) {
            s += __shfl_xor_sync(FULL, s, o);
            c += __shfl_xor_sync(FULL, c, o);
        }
        __shared__ float ss[8], cc2[8];
        if (lane == 0) { ss[widx] = s; cc2[widx] = c; }
        __syncthreads();
        if (tid == 0) {
            float ts = 0.f, tc = 0.f;
            #pragma unroll
            for (int i = 0; i < 8; i++) { ts += ss[i]; tc += cc2[i]; }
            out[0] = ts / tc;
            g_arrive = 0;   // reset for next graph replay
            g_done   = 0;
        }
    }
}

// ---------------------------------------------------------------------------
extern "C" void kernel_launch(void* const* d_in, const int* in_sizes, int n_in,
                              void* d_out, int out_size) {
    const float* emb = (const float*)d_in[0];
    const int* labels = (const int*)d_in[1];
    float* out = (float*)d_out;

    triplet_fused<<<NBLK, 256>>>(emb, labels, out);
}

// round 7
// speedup vs baseline: 1.1371x; 1.1371x over previous
#include <cuda_runtime.h>
#include <float.h>

#define BN 512
#define DN 256
#define NT 16            // 512 / 32 tiles per dim
#define NBLK 136         // NT*(NT+1)/2 upper-triangular tiles
#define MBLK 128         // mine kernel CTAs (4 warps = 4 anchors each)

// Scratch (no allocations allowed)
__device__ float g_pd[BN * BN];
__device__ float g_ploss[BN];
__device__ int   g_pcnt[BN];
__device__ unsigned int g_done;    // reset by last CTA each call

// ---------------------------------------------------------------------------
// Kernel A: symmetric pairwise sq-distance GEMM, norms fused into tile loads.
// 136 CTAs x 256 threads, split-K x4 (4 groups x 64 threads), 4x4 microtile.
// ---------------------------------------------------------------------------
__global__ void __launch_bounds__(256) pd_fused(const float* __restrict__ emb) {
    __shared__ float As[4][32][32];   // reused as partial-sum scratch after loop
    __shared__ float Bs[4][32][32];
    __shared__ float nA[4][32], nB[4][32];
    __shared__ float sqA[32], sqB[32];

    const int tid = threadIdx.x;

    // decode linear block -> (ti, tj), ti <= tj
    int b = blockIdx.x, ti = 0;
    while (b >= NT - ti) { b -= NT - ti; ti++; }
    const int tj = ti + b;
    const int i0 = ti * 32, j0 = tj * 32;

    const int t    = tid & 63;
    const int g    = tid >> 6;             // 0..3, k in [g*64, g*64+64)
    const int lr   = t >> 1;               // load row 0..31
    const int half = t & 1;                // k-half within 32-chunk
    const int ty   = t >> 3;               // 0..7 -> 4 i-rows
    const int tx   = t & 7;                // 0..7 -> 4 j-cols

    float acc[4][4] = {};
    float na = 0.f, nb = 0.f;              // norm partials (32 ks of row lr)

    {
        const float* Arow = emb + (i0 + lr) * DN + g * 64;
        const float* Brow = emb + (j0 + lr) * DN + g * 64;

        #pragma unroll
        for (int c0 = 0; c0 < 64; c0 += 32) {
            __syncthreads();
            #pragma unroll
            for (int e = 0; e < 4; e++) {
                const int ko = half * 16 + e * 4;
                float4 a4 = *(const float4*)(Arow + c0 + ko);
                float4 b4 = *(const float4*)(Brow + c0 + ko);
                na = fmaf(a4.x, a4.x, fmaf(a4.y, a4.y, fmaf(a4.z, a4.z, fmaf(a4.w, a4.w, na))));
                nb = fmaf(b4.x, b4.x, fmaf(b4.y, b4.y, fmaf(b4.z, b4.z, fmaf(b4.w, b4.w, nb))));
                As[g][ko + 0][lr] = a4.x; As[g][ko + 1][lr] = a4.y;
                As[g][ko + 2][lr] = a4.z; As[g][ko + 3][lr] = a4.w;
                Bs[g][ko + 0][lr] = b4.x; Bs[g][ko + 1][lr] = b4.y;
                Bs[g][ko + 2][lr] = b4.z; Bs[g][ko + 3][lr] = b4.w;
            }
            __syncthreads();
            #pragma unroll
            for (int kk = 0; kk < 32; kk++) {
                float4 av = *(const float4*)&As[g][kk][ty << 2];
                float4 bv = *(const float4*)&Bs[g][kk][tx << 2];
                float ar[4] = {av.x, av.y, av.z, av.w};
                float br[4] = {bv.x, bv.y, bv.z, bv.w};
                #pragma unroll
                for (int u = 0; u < 4; u++)
                    #pragma unroll
                    for (int v = 0; v < 4; v++)
                        acc[u][v] = fmaf(ar[u], br[v], acc[u][v]);
            }
        }
    }

    // ---- norm combine: lanes (2m, 2m+1) share row lr ----
    na += __shfl_xor_sync(0xffffffffu, na, 1);
    nb += __shfl_xor_sync(0xffffffffu, nb, 1);
    if (!half) { nA[g][lr] = na; nB[g][lr] = nb; }
    __syncthreads();
    if (g == 0) {
        if (t < 32) sqA[t] = (nA[0][t] + nA[1][t]) + (nA[2][t] + nA[3][t]);
        else        sqB[t - 32] = (nB[0][t - 32] + nB[1][t - 32]) + (nB[2][t - 32] + nB[3][t - 32]);
    }
    // groups 1..3 park their partials in As-scratch (disjoint from sqA/sqB)
    if (g > 0) {
        float* dst = &As[0][0][0] + ((g - 1) * 64 + t) * 16;
        #pragma unroll
        for (int u = 0; u < 4; u++)
            #pragma unroll
            for (int v = 0; v < 4; v++) dst[u * 4 + v] = acc[u][v];
    }
    __syncthreads();

    if (g == 0) {
        const float* p1 = &As[0][0][0] + (0 * 64 + t) * 16;
        const float* p2 = &As[0][0][0] + (1 * 64 + t) * 16;
        const float* p3 = &As[0][0][0] + (2 * 64 + t) * 16;
        float d[4][4];
        #pragma unroll
        for (int u = 0; u < 4; u++) {
            const int gi = i0 + (ty << 2) + u;
            const float sqi = sqA[(ty << 2) + u];
            #pragma unroll
            for (int v = 0; v < 4; v++) {
                const int gj = j0 + (tx << 2) + v;
                const int e = u * 4 + v;
                const float dot = (acc[u][v] + p1[e]) + (p2[e] + p3[e]);
                float val = fmaxf(sqi + sqB[(tx << 2) + v] - 2.f * dot, 0.f);
                if (gi == gj) val = 0.f;
                d[u][v] = val;
            }
            *(float4*)(g_pd + gi * BN + j0 + (tx << 2)) =
                make_float4(d[u][0], d[u][1], d[u][2], d[u][3]);
        }
        if (ti != tj) {
            #pragma unroll
            for (int v = 0; v < 4; v++) {
                const int gj = j0 + (tx << 2) + v;
                *(float4*)(g_pd + gj * BN + i0 + (ty << 2)) =
                    make_float4(d[0][v], d[1][v], d[2][v], d[3][v]);
            }
        }
    }
}

// ---------------------------------------------------------------------------
// Kernel B: warp-per-anchor semi-hard mining + fused final reduction.
// 128 CTAs x 128 threads; warp w of CTA cb owns anchor j = cb*4 + w.
// ---------------------------------------------------------------------------
__global__ void __launch_bounds__(128) mine_final(const int* __restrict__ labels,
                                                  float* __restrict__ out) {
    const int tid = threadIdx.x;
    const int lane = tid & 31, w = tid >> 5;
    const unsigned FULL = 0xffffffffu;

    __shared__ int   s_lab[BN];
    __shared__ float s_row[4][BN];
    __shared__ int s_last;

    #pragma unroll
    for (int k = tid; k < BN; k += 128) s_lab[k] = labels[k];
    __syncthreads();

    const int j = blockIdx.x * 4 + w;          // anchor (0..511)
    const int lj = s_lab[j];
    const float* rowp = g_pd + j * BN;

    // load row into registers + smem; build negativity/positivity masks
    float v[16];
    unsigned nmask = 0, pmask = 0;
    #pragma unroll
    for (int c = 0; c < 16; c++) {
        const int k = c * 32 + lane;
        v[c] = rowp[k];
        s_row[w][k] = v[c];
        const bool same = (s_lab[k] == lj);
        if (!same) nmask |= (1u << c);
        if (same && k != j) pmask |= (1u << c);
    }

    // neg_inside: max over negatives (fallback: min over full row)
    float mx = -FLT_MAX, mn = FLT_MAX;
    #pragma unroll
    for (int c = 0; c < 16; c++) {
        if ((nmask >> c) & 1) mx = fmaxf(mx, v[c]);
        mn = fminf(mn, v[c]);
    }
    #pragma unroll
    for (int o = 16; o; o >>= 1) {
        mx = fmaxf(mx, __shfl_xor_sync(FULL, mx, o));
        mn = fminf(mn, __shfl_xor_sync(FULL, mn, o));
    }
    const float ninside = (mx > -FLT_MAX) ? mx : mn;

    // iterate positives deterministically, process in pairs (overlap shfl chains)
    float wsum = 0.f;
    int cnt = 0;
    int pend = -1;
    #pragma unroll 1
    for (int c = 0; c < 16; c++) {
        unsigned pm = __ballot_sync(FULL, (pmask >> c) & 1);
        while (pm) {
            const int bb = __ffs(pm) - 1;
            pm &= pm - 1;
            const int i = c * 32 + bb;
            cnt++;
            if (pend < 0) { pend = i; continue; }
            const float t1 = s_row[w][pend];
            const float t2 = s_row[w][i];
            float m1 = FLT_MAX, m2 = FLT_MAX;
            #pragma unroll
            for (int cc = 0; cc < 16; cc++) {
                if ((nmask >> cc) & 1) {
                    const float x = v[cc];
                    if (x > t1) m1 = fminf(m1, x);
                    if (x > t2) m2 = fminf(m2, x);
                }
            }
            #pragma unroll
            for (int o = 16; o; o >>= 1) {
                m1 = fminf(m1, __shfl_xor_sync(FULL, m1, o));
                m2 = fminf(m2, __shfl_xor_sync(FULL, m2, o));
            }
            const float semi1 = (m1 < FLT_MAX) ? m1 : ninside;
            const float semi2 = (m2 < FLT_MAX) ? m2 : ninside;
            wsum += fmaxf(1.0f + t1 - semi1, 0.f);
            wsum += fmaxf(1.0f + t2 - semi2, 0.f);
            pend = -1;
        }
    }
    if (pend >= 0) {
        const float t1 = s_row[w][pend];
        float m1 = FLT_MAX;
        #pragma unroll
        for (int cc = 0; cc < 16; cc++) {
            if ((nmask >> cc) & 1) {
                const float x = v[cc];
                if (x > t1) m1 = fminf(m1, x);
            }
        }
        #pragma unroll
        for (int o = 16; o; o >>= 1)
            m1 = fminf(m1, __shfl_xor_sync(FULL, m1, o));
        const float semi1 = (m1 < FLT_MAX) ? m1 : ninside;
        wsum += fmaxf(1.0f + t1 - semi1, 0.f);
    }

    if (lane == 0) {
        g_ploss[j] = wsum;
        g_pcnt[j]  = cnt;
    }
    __syncthreads();
    if (tid == 0) {
        __threadfence();
        const unsigned int vd = atomicAdd(&g_done, 1u);
        s_last = (vd == (unsigned)(gridDim.x - 1)) ? 1 : 0;
    }
    __syncthreads();

    // last CTA: deterministic final reduction over fixed-order arrays
    if (s_last) {
        __threadfence();  // acquire
        float s = 0.f, c = 0.f;
        #pragma unroll
        for (int r = 0; r < 4; r++) {
            s += g_ploss[tid + r * 128];
            c += (float)g_pcnt[tid + r * 128];
        }
        #pragma unroll
        for (int o = 16; o; o >>= 1) {
            s += __shfl_xor_sync(FULL, s, o);
            c += __shfl_xor_sync(FULL, c, o);
        }
        __shared__ float ss[4], cc2[4];
        if (lane == 0) { ss[w] = s; cc2[w] = c; }
        __syncthreads();
        if (tid == 0) {
            float ts = 0.f, tc = 0.f;
            #pragma unroll
            for (int i = 0; i < 4; i++) { ts += ss[i]; tc += cc2[i]; }
            out[0] = ts / tc;
            g_done = 0;   // reset for next graph replay
        }
    }
}

// ---------------------------------------------------------------------------
extern "C" void kernel_launch(void* const* d_in, const int* in_sizes, int n_in,
                              void* d_out, int out_size) {
    const float* emb = (const float*)d_in[0];
    const int* labels = (const int*)d_in[1];
    float* out = (float*)d_out;

    pd_fused<<<NBLK, 256>>>(emb);
    mine_final<<<MBLK, 128>>>(labels, out);
}